// round 17
// baseline (speedup 1.0000x reference)
#include <cuda_runtime.h>
#include <math.h>

#define V_NODES 2048
#define D_F     128
#define NJ      8
#define NCHUNK  128                  // CTAs; 16 rows/chunk each
#define VC      16
#define NP      73                   // 1 + J + J^2 output planes
#define NPU     45                   // 1 + J + 36 unique planes
#define PLANE_ELEMS (NPU * D_F)      // 5760
#define NGROUP  8                    // 16 chunks per group
#define THREADS 1024

__device__ float        g_partial[NCHUNK * PLANE_ELEMS];  // per-chunk partials
__device__ float        g_p2[NGROUP * PLANE_ELEMS];       // per-group partials
__device__ unsigned int g_gcnt[NGROUP];                   // group tickets
__device__ unsigned int g_cnt2;                           // final ticket

// triangle decode for planes 9..44 (lo-major upper triangle)
__device__ const int TJ1[36] = {0,0,0,0,0,0,0,0, 1,1,1,1,1,1,1, 2,2,2,2,2,2,
                                3,3,3,3,3, 4,4,4,4, 5,5,5, 6,6, 7};
__device__ const int TJ2[36] = {0,1,2,3,4,5,6,7, 1,2,3,4,5,6,7, 2,3,4,5,6,7,
                                3,4,5,6,7, 4,5,6,7, 5,6,7, 6,7, 7};

__global__ void __launch_bounds__(THREADS, 1)
k_all(const float* __restrict__ W, const float* __restrict__ f,
      float* __restrict__ out) {
    __shared__ float sl[NJ][VC];        // filter responses per chunk row
    __shared__ float sf[VC][D_F];       // f chunk (signed)
    __shared__ float wp[NPU][VC];       // per-plane weight products (plane0 unused)
    __shared__ float sw[32];
    __shared__ int   stk, stk2;

    const int tid  = threadIdx.x;
    const int warp = tid >> 5;
    const int lane = tid & 31;
    const int c    = blockIdx.x;

    // -------- issue f loads for this chunk up front (hidden under phase A) --
    float fv0 = f[(size_t)c * (VC * D_F) + tid];
    float fv1 = f[(size_t)c * (VC * D_F) + THREADS + tid];

    // -------- phase A: stream 16 rows of W, compute deg + filters ----------
    {
        const int rib = warp >> 1;             // row in chunk (0..15)
        const int par = warp & 1;              // row half
        const int row = c * VC + rib;
        const float4* Wr = reinterpret_cast<const float4*>(W + (size_t)row * V_NODES);
        float4 x[8];
        #pragma unroll
        for (int i = 0; i < 8; i++)            // front-batched MLP=8
            x[i] = Wr[lane + 32 * par + 64 * i];
        float s = 0.f;
        #pragma unroll
        for (int i = 0; i < 8; i++)
            s += ((x[i].x + x[i].y) + (x[i].z + x[i].w));
        #pragma unroll
        for (int off = 16; off; off >>= 1) s += __shfl_down_sync(0xffffffffu, s, off);
        if (lane == 0) sw[warp] = s;
    }
    // stage f chunk into smem (signed)
    sf[tid >> 7][tid & 127]       = fv0;
    sf[8 + (tid >> 7)][tid & 127] = fv1;
    __syncthreads();

    if (tid < VC) {
        float deg = sw[2 * tid] + sw[2 * tid + 1];
        // Lmat diag = deg * dhalf^2, dhalf^2 = 1/max(1,deg); E = |.|
        float dh2  = 1.0f / fmaxf(1.0f, deg);
        float E    = fabsf(deg * dh2);
        float logE = logf(E);
        const float A   = 3.0f * 0.69314718055994531f / 6.0f;  // R*ln2/(J-R+1)
        const float PI2 = 6.28318530717958648f;
        float ssum = 1.125f;                    // (R/2)sum(d^2) + (R/2)d0^2
        #pragma unroll
        for (int j = 2; j <= NJ; j++) {
            float xx  = logE - A * (float)(j - 1) / 3.0f;
            float wav = 0.0f;
            if (xx > -A && xx <= 0.0f)
                wav = 0.5f - 0.5f * cosf(PI2 * xx / A);  // d=(.5,.5),K=1
            ssum -= wav * wav;
            sl[j - 1][tid] = wav;
        }
        sl[0][tid] = sqrtf(fmaxf(ssum, 0.0f));
    }
    __syncthreads();

    // weight products: planes 1..8 = lam_j; planes 9..44 = lam_j1*lam_j2
    if (tid < (NPU - 1) * VC) {                 // 704 threads
        int p = 1 + (tid >> 4), v = tid & 15;
        float w;
        if (p <= NJ) {
            w = sl[p - 1][v];
        } else {
            int i = p - 1 - NJ;
            w = sl[TJ1[i]][v] * sl[TJ2[i]][v];
        }
        wp[p][v] = w;
    }
    __syncthreads();

    // -------- phase B: (plane,d)-per-thread partials over the 16 nodes -----
    float* pp = g_partial + (size_t)c * PLANE_ELEMS;
    #pragma unroll
    for (int idx = tid; idx < PLANE_ELEMS; idx += THREADS) {
        int p = idx >> 7, d = idx & 127;
        float acc = 0.f;
        if (p == 0) {
            #pragma unroll
            for (int v = 0; v < VC; v++) acc += sf[v][d];
        } else {
            #pragma unroll
            for (int v = 0; v < VC; v++) acc += wp[p][v] * fabsf(sf[v][d]);
        }
        pp[idx] = acc;
    }

    // -------- ticket cascade: deterministic fixed-order reduction ----------
    __syncthreads();
    if (tid == 0) {
        __threadfence();                        // my partials visible first
        stk = (int)atomicAdd(&g_gcnt[c >> 4], 1u);
    }
    __syncthreads();
    if (stk != 15) return;                      // not the group's last arriver

    // group reducer: sum the 16 chunk partials of group g in fixed order
    const int g = c >> 4;
    __threadfence();
    for (int idx = tid; idx < PLANE_ELEMS; idx += THREADS) {
        float s = 0.f;
        #pragma unroll
        for (int k = 0; k < 16; k++)
            s += __ldcg(&g_partial[(size_t)(g * 16 + k) * PLANE_ELEMS + idx]);
        g_p2[(size_t)g * PLANE_ELEMS + idx] = s;
    }
    __syncthreads();
    if (tid == 0) {
        __threadfence();
        stk2 = (int)atomicAdd(&g_cnt2, 1u);
    }
    __syncthreads();
    if (stk2 != NGROUP - 1) return;             // not the last group reducer

    // final: 8-way fixed-order sum, expand 45 unique -> 73 planes, scale
    __threadfence();
    const float inv = 1.0f / (float)V_NODES;
    for (int idx = tid; idx < NP * D_F; idx += THREADS) {
        int p = idx >> 7, d = idx & 127;
        int plane;
        if (p < 1 + NJ) {
            plane = p;
        } else {
            int qq = p - (1 + NJ);
            int j1 = qq >> 3, j2 = qq & 7;
            int lo = j1 < j2 ? j1 : j2;
            int hi = j1 < j2 ? j2 : j1;
            plane = 1 + NJ + lo * NJ - (lo * (lo - 1)) / 2 + (hi - lo);
        }
        float s = 0.f;
        #pragma unroll
        for (int k = 0; k < NGROUP; k++)
            s += __ldcg(&g_p2[(size_t)k * PLANE_ELEMS + plane * D_F + d]);
        out[idx] = s * inv;
    }
    // reset counters for the next graph replay
    if (tid < NGROUP) g_gcnt[tid] = 0u;
    if (tid == 0)     g_cnt2 = 0u;
}

// ---------------------------------------------------------------------------
extern "C" void kernel_launch(void* const* d_in, const int* in_sizes, int n_in,
                              void* d_out, int out_size) {
    const float* W = (const float*)d_in[0];
    const float* f = (const float*)d_in[1];
    if (n_in >= 2 && in_sizes[0] != V_NODES * V_NODES) {
        W = (const float*)d_in[1];
        f = (const float*)d_in[0];
    }
    k_all<<<NCHUNK, THREADS>>>(W, f, (float*)d_out);
}